// round 10
// baseline (speedup 1.0000x reference)
#include <cuda_runtime.h>
#include <cuda_fp16.h>
#include <cstdint>

#define NN 100000
#define NPAD 100096   // 782 * 128
#define EE 1600000
#define FIN 32
#define DD 128
#define LL 5
#define BB 3000
#define VV 64
#define TT 128
#define EMBD 64
#define HH 640      // L*D LSTM hidden
#define G4 2560     // 4*H
#define MPAD 3072   // 24 * 128

// ---------------- scratch (device globals; no allocation allowed) ----------------
__device__ float d_h[NN * DD];
__device__ float d_z[NN * DD];
__device__ int   d_deg[NN];
__device__ int   d_rowptr[NN + 1];
__device__ int   d_cursor[NN];
__device__ int   d_col[EE];
__device__ int   d_bsum[256];
__device__ float d_stat[1024];
__device__ float d_mu[512];
__device__ float d_rstd[512];
__device__ float d_enc1[BB * HH];
__device__ float d_tok[VV * G4];          // interleaved: col j = ch*4+gate
__device__ float d_hl[BB * HH];
__device__ float d_cl[BB * HH];
__device__ float d_proj[BB * 512];
__device__ float d_head[BB * 768];
__device__ __half d_whh[G4 * HH];         // fp16-rounded Whh (interleaved rows, K-major)
__device__ __half d_hh[2 * MPAD * HH];    // ping-pong h (read t&1, write (t+1)&1)
// GIN fp16 scratch (padded rows stay zero)
__device__ __half d_zh[NPAD * DD];
__device__ __half d_zl[NPAD * DD];
__device__ __half d_t1h[NPAD * DD];
__device__ __half d_t1l[NPAD * DD];
__device__ __half d_wth[DD * DD];         // W^T hi  [N=128, K]
__device__ __half d_wtl[DD * DD];         // W^T lo

// ================= PTX helpers (compute_100-safe: cp.async / ldmatrix / mma.sync) ======
__device__ __forceinline__ uint32_t smem_u32(const void* p) {
    uint32_t a;
    asm("{ .reg .u64 t; cvta.to.shared.u64 t, %1; cvt.u32.u64 %0, t; }" : "=r"(a) : "l"(p));
    return a;
}

#define CPASYNC16(dst, src) \
    asm volatile("cp.async.cg.shared.global [%0], [%1], 16;" :: "r"(dst), "l"(src))

__device__ __forceinline__ void ldmx4(uint32_t* r, uint32_t addr) {
    asm volatile("ldmatrix.sync.aligned.m8n8.x4.shared.b16 {%0,%1,%2,%3}, [%4];"
        : "=r"(r[0]), "=r"(r[1]), "=r"(r[2]), "=r"(r[3]) : "r"(addr));
}

__device__ __forceinline__ void mma16816(float* c, const uint32_t* a, const uint32_t* b) {
    asm volatile("mma.sync.aligned.m16n8k16.row.col.f32.f16.f16.f32 "
        "{%0,%1,%2,%3}, {%4,%5,%6,%7}, {%8,%9}, {%0,%1,%2,%3};"
        : "+f"(c[0]), "+f"(c[1]), "+f"(c[2]), "+f"(c[3])
        : "r"(a[0]), "r"(a[1]), "r"(a[2]), "r"(a[3]), "r"(b[0]), "r"(b[1]));
}

// ---------------- CSR build ----------------
__global__ void k_count(const int* __restrict__ dst) {
    int e = blockIdx.x * blockDim.x + threadIdx.x;
    if (e < EE) atomicAdd(&d_deg[dst[e]], 1);
}

__global__ void k_scan1() {
    __shared__ int s[1024];
    int i = blockIdx.x * 1024 + threadIdx.x;
    int v = (i < NN) ? d_deg[i] : 0;
    s[threadIdx.x] = v;
    __syncthreads();
    for (int off = 1; off < 1024; off <<= 1) {
        int t = (threadIdx.x >= off) ? s[threadIdx.x - off] : 0;
        __syncthreads();
        s[threadIdx.x] += t;
        __syncthreads();
    }
    if (i < NN) d_rowptr[i] = s[threadIdx.x];
    if (threadIdx.x == 1023) d_bsum[blockIdx.x] = s[1023];
}

__global__ void k_scan2(int nb) {
    if (threadIdx.x == 0 && blockIdx.x == 0) {
        int acc = 0;
        for (int i = 0; i < nb; i++) { int v = d_bsum[i]; d_bsum[i] = acc; acc += v; }
    }
}

__global__ void k_scan3() {
    int i = blockIdx.x * blockDim.x + threadIdx.x;
    if (i < NN) {
        int start = d_rowptr[i] + d_bsum[i >> 10] - d_deg[i];
        d_rowptr[i] = start;
        d_cursor[i] = start;
        if (i == 0) d_rowptr[NN] = EE;
    }
}

__global__ void k_fill(const int* __restrict__ src, const int* __restrict__ dst) {
    int e = blockIdx.x * blockDim.x + threadIdx.x;
    if (e < EE) {
        int p = atomicAdd(&d_cursor[dst[e]], 1);
        d_col[p] = src[e];
    }
}

// ---------------- GIN gather: z = h + sum_{j->i} h_j, emitted as fp16 hi/lo ----------
template <int D4P>
__global__ void k_gather16(const float* __restrict__ hin,
                           __half* __restrict__ zh, __half* __restrict__ zl) {
    int idx = blockIdx.x * blockDim.x + threadIdx.x;
    if (idx >= NN * D4P) return;
    int n = idx / D4P, c = idx % D4P;
    const float4* H = (const float4*)hin;
    float4 a = H[(size_t)n * D4P + c];
    int p1 = d_rowptr[n + 1];
    for (int p = d_rowptr[n]; p < p1; p++) {
        int s = d_col[p];
        float4 b = __ldg(&H[(size_t)s * D4P + c]);
        a.x += b.x; a.y += b.y; a.z += b.z; a.w += b.w;
    }
    alignas(8) __half h4[4], l4[4];
    float v[4] = {a.x, a.y, a.z, a.w};
#pragma unroll
    for (int j = 0; j < 4; j++) {
        __half hi = __float2half(v[j]);
        h4[j] = hi;
        l4[j] = __float2half(v[j] - __half2float(hi));
    }
    ((uint2*)zh)[idx] = *(const uint2*)h4;
    ((uint2*)zl)[idx] = *(const uint2*)l4;
}

// ---------------- weight transpose + exact fp16 hi/lo split: W[K,128] -> wt[128,K] ----
__global__ void k_wt16(const float* __restrict__ W, int K) {
    int idx = blockIdx.x * blockDim.x + threadIdx.x;
    if (idx >= 128 * K) return;
    int n = idx / K, k = idx % K;
    float v = W[(size_t)k * 128 + n];
    __half hi = __float2half(v);
    d_wth[idx] = hi;
    d_wtl[idx] = __float2half(v - __half2float(hi));
}

// ---------------- GIN fp16x3 GEMM: out = relu(A[M,K] @ Wt^T + bias), N=128 -----------
// grid (1, 782), 256 thr, 8 warps (2x4). CTA tile M=128, N=128. 3 mma passes.
#define GSTG 10240      // one stage buffer: 128 rows x 80B (32 fp16 + 8 pad)

__global__ __launch_bounds__(256, 1) void k_gemm16(
    const __half* __restrict__ Ah, const __half* __restrict__ Al,
    const float* __restrict__ bias,
    __half* __restrict__ outh, __half* __restrict__ outl,
    float* __restrict__ outf, int K)
{
    extern __shared__ char dsm[];
    uint32_t sb = smem_u32(dsm);
    int nk = K / 32;
    int tid = threadIdx.x;
    int warp = tid >> 5, lane = tid & 31;
    int m0 = blockIdx.y * 128;
    int warp_m0 = (warp >> 2) * 64, warp_n0 = (warp & 3) * 32;

    // slot layout: [slot*40960): Ah +0, Al +10240, Bh +20480, Bl +30720
    auto issue = [&](int s) {
        if (s >= nk) return;
        int k0 = s * 32;
        uint32_t base = sb + (uint32_t)(s & 1) * 4 * GSTG;
#pragma unroll
        for (int i = 0; i < 2; i++) {
            int ch = tid + i * 256;
            int r = ch >> 3, c = ch & 7;  // wrong split for 512? careful below
            (void)r; (void)c;
        }
        // A: 128 rows x 4 chunks of 16B
#pragma unroll
        for (int i = 0; i < 2; i++) {
            int ch = tid + i * 256;       // 0..511
            int r = ch >> 2, c = ch & 3;
            uint32_t doff = (uint32_t)(r * 80 + c * 16);
            CPASYNC16(base + doff, Ah + (size_t)(m0 + r) * K + k0 + c * 8);
            CPASYNC16(base + 10240 + doff, Al + (size_t)(m0 + r) * K + k0 + c * 8);
            CPASYNC16(base + 20480 + doff, d_wth + (size_t)r * K + k0 + c * 8);
            CPASYNC16(base + 30720 + doff, d_wtl + (size_t)r * K + k0 + c * 8);
        }
    };

    float acc[4][4][4];
#pragma unroll
    for (int i = 0; i < 4; i++)
#pragma unroll
        for (int j = 0; j < 4; j++)
#pragma unroll
            for (int q = 0; q < 4; q++) acc[i][j][q] = 0.f;

    issue(0);
    asm volatile("cp.async.commit_group;");
    issue(1);
    asm volatile("cp.async.commit_group;");

    int lrow = lane & 7, grp = lane >> 3;

    for (int s = 0; s < nk; s++) {
        asm volatile("cp.async.wait_group 1;" ::: "memory");
        __syncthreads();
        uint32_t base = sb + (uint32_t)(s & 1) * 4 * GSTG;
        uint32_t sAh = base, sAl = base + 10240, sBh = base + 20480, sBl = base + 30720;

#pragma unroll
        for (int kk = 0; kk < 2; kk++) {
            uint32_t a_hi[4][4], a_lo[4][4];
#pragma unroll
            for (int mt = 0; mt < 4; mt++) {
                uint32_t ra = (uint32_t)(warp_m0 + mt * 16 + ((grp & 1) << 3) + lrow);
                uint32_t ca = (uint32_t)(kk * 16 + ((grp >> 1) << 3));
                uint32_t off = ra * 80 + ca * 2;
                ldmx4(a_hi[mt], sAh + off);
                ldmx4(a_lo[mt], sAl + off);
            }
            uint32_t b_hi[4][2], b_lo[4][2];
#pragma unroll
            for (int nt2 = 0; nt2 < 2; nt2++) {
                uint32_t rb = (uint32_t)(warp_n0 + nt2 * 16 + ((grp >> 1) << 3) + lrow);
                uint32_t cb = (uint32_t)(kk * 16 + ((grp & 1) << 3));
                uint32_t off = rb * 80 + cb * 2;
                uint32_t rh[4], rl[4];
                ldmx4(rh, sBh + off);
                ldmx4(rl, sBl + off);
                b_hi[nt2 * 2 + 0][0] = rh[0]; b_hi[nt2 * 2 + 0][1] = rh[1];
                b_hi[nt2 * 2 + 1][0] = rh[2]; b_hi[nt2 * 2 + 1][1] = rh[3];
                b_lo[nt2 * 2 + 0][0] = rl[0]; b_lo[nt2 * 2 + 0][1] = rl[1];
                b_lo[nt2 * 2 + 1][0] = rl[2]; b_lo[nt2 * 2 + 1][1] = rl[3];
            }
#pragma unroll
            for (int mt = 0; mt < 4; mt++)
#pragma unroll
                for (int nt = 0; nt < 4; nt++) {
                    mma16816(acc[mt][nt], a_hi[mt], b_hi[nt]);
                    mma16816(acc[mt][nt], a_hi[mt], b_lo[nt]);
                    mma16816(acc[mt][nt], a_lo[mt], b_hi[nt]);
                }
        }
        __syncthreads();
        issue(s + 2);
        asm volatile("cp.async.commit_group;");
    }

    // ---- epilogue: bias + relu, direct register -> global ----
    int lrow4 = lane >> 2, lcol2 = (lane & 3) * 2;
#pragma unroll
    for (int mt = 0; mt < 4; mt++)
#pragma unroll
        for (int nt = 0; nt < 4; nt++) {
            int col = warp_n0 + nt * 8 + lcol2;
            float b0 = __ldg(&bias[col]), b1v = __ldg(&bias[col + 1]);
#pragma unroll
            for (int hr = 0; hr < 2; hr++) {
                int m = m0 + warp_m0 + mt * 16 + lrow4 + hr * 8;
                if (m >= NN) continue;
                float v0 = fmaxf(acc[mt][nt][hr * 2 + 0] + b0, 0.f);
                float v1 = fmaxf(acc[mt][nt][hr * 2 + 1] + b1v, 0.f);
                if (outf) {
                    *(float2*)(outf + (size_t)m * 128 + col) = make_float2(v0, v1);
                } else {
                    __half h0 = __float2half(v0), h1 = __float2half(v1);
                    __half l0 = __float2half(v0 - __half2float(h0));
                    __half l1 = __float2half(v1 - __half2float(h1));
                    alignas(4) __half hp[2] = {h0, h1}, lp[2] = {l0, l1};
                    *(uint32_t*)(outh + (size_t)m * 128 + col) = *(const uint32_t*)hp;
                    *(uint32_t*)(outl + (size_t)m * 128 + col) = *(const uint32_t*)lp;
                }
            }
        }
}

// ---------------- Generic fp32 GEMM (heads): C = act(A[M,K] @ W[K,N] + bias) ---------
__global__ __launch_bounds__(256) void k_gemm(const float* __restrict__ A,
                                              const float* __restrict__ W,
                                              const float* __restrict__ bias,
                                              float* __restrict__ C,
                                              int M, int N, int K, int relu) {
    __shared__ float As[16][132];
    __shared__ float Bs[16][132];
    int tid = threadIdx.x;
    int m0 = blockIdx.y * 128, n0 = blockIdx.x * 128;
    int ty = tid >> 4, tx = tid & 15;
    float acc[8][8];
#pragma unroll
    for (int i = 0; i < 8; i++)
#pragma unroll
        for (int j = 0; j < 8; j++) acc[i][j] = 0.f;

    for (int k0 = 0; k0 < K; k0 += 16) {
#pragma unroll
        for (int i = 0; i < 2; i++) {
            int lin = tid + i * 256;
            int r = lin >> 2, c4 = lin & 3;
            float4 v = make_float4(0.f, 0.f, 0.f, 0.f);
            if (m0 + r < M) v = *(const float4*)(A + (size_t)(m0 + r) * K + k0 + c4 * 4);
            As[c4 * 4 + 0][r] = v.x; As[c4 * 4 + 1][r] = v.y;
            As[c4 * 4 + 2][r] = v.z; As[c4 * 4 + 3][r] = v.w;
        }
#pragma unroll
        for (int i = 0; i < 2; i++) {
            int lin = tid + i * 256;
            int kk = lin >> 5, n4 = lin & 31;
            float4 v = *(const float4*)(W + (size_t)(k0 + kk) * N + n0 + n4 * 4);
            *(float4*)&Bs[kk][n4 * 4] = v;
        }
        __syncthreads();
#pragma unroll
        for (int k = 0; k < 16; k++) {
            float4 a0 = *(const float4*)&As[k][ty * 4];
            float4 a1 = *(const float4*)&As[k][64 + ty * 4];
            float4 b0 = *(const float4*)&Bs[k][tx * 4];
            float4 b1 = *(const float4*)&Bs[k][64 + tx * 4];
            float a[8] = {a0.x, a0.y, a0.z, a0.w, a1.x, a1.y, a1.z, a1.w};
            float b[8] = {b0.x, b0.y, b0.z, b0.w, b1.x, b1.y, b1.z, b1.w};
#pragma unroll
            for (int i = 0; i < 8; i++)
#pragma unroll
                for (int j = 0; j < 8; j++) acc[i][j] += a[i] * b[j];
        }
        __syncthreads();
    }
#pragma unroll
    for (int i = 0; i < 8; i++) {
        int m = m0 + ((i < 4) ? ty * 4 + i : 64 + ty * 4 + (i - 4));
        if (m >= M) continue;
#pragma unroll
        for (int j = 0; j < 8; j++) {
            int n = n0 + ((j < 4) ? tx * 4 + j : 64 + tx * 4 + (j - 4));
            float v = acc[i][j];
            if (bias) v += __ldg(&bias[n]);
            if (relu) v = fmaxf(v, 0.f);
            C[(size_t)m * N + n] = v;
        }
    }
}

// ---------------- prep: interleaved fp16-rounded Whh ----------------
__global__ void k_whh_split(const float* __restrict__ whh) {
    int idx = blockIdx.x * blockDim.x + threadIdx.x;
    if (idx >= G4 * HH) return;
    int j = idx / HH, k = idx % HH;
    int gate = j & 3, ch = j >> 2;
    d_whh[idx] = __float2half(whh[(size_t)(gate * HH + ch) * HH + k]);
}

// token gate table, gate-interleaved columns: j = ch*4+gate
__global__ void k_tok(const float* __restrict__ emb, const float* __restrict__ wih,
                      const float* __restrict__ bih, const float* __restrict__ bhh) {
    int idx = blockIdx.x * blockDim.x + threadIdx.x;
    if (idx >= VV * G4) return;
    int v = idx / G4, j = idx % G4;
    int row = (j & 3) * HH + (j >> 2);
    float s = bih[row] + bhh[row];
#pragma unroll 16
    for (int k = 0; k < EMBD; k++) s += emb[v * EMBD + k] * wih[row * EMBD + k];
    d_tok[idx] = s;
}

__device__ __forceinline__ float sigf(float x) {
    return __fdividef(1.f, 1.f + __expf(-x));
}
__device__ __forceinline__ float tanhf_fast(float x) {
    return 1.f - __fdividef(2.f, __expf(2.f * x) + 1.f);
}

// ---------------- fused LSTM step (R7 config): mma.sync fp16 + gate update ------------
// grid (20, 24), 256 threads (8 warps, 2x4). CTA tile: M=128 rows, N=128 cols
#define STG_B 10240
#define CST 132

__global__ __launch_bounds__(256, 2) void k_lstm_step(
    const int* __restrict__ smi,
    const __half* __restrict__ hin,
    __half* __restrict__ hout,
    int t, int last)
{
    extern __shared__ char dsm[];
    uint32_t sb = smem_u32(dsm);
    uint32_t sA = sb, sB = sb + 2 * STG_B;
    float* Csm = (float*)dsm;

    int tid = threadIdx.x;
    int warp = tid >> 5, lane = tid & 31;
    int m0 = blockIdx.y * 128, n0 = blockIdx.x * 128;
    int warp_m0 = (warp >> 2) * 64, warp_n0 = (warp & 3) * 32;

    auto issue = [&](int s) {
        int k0 = s * 32;
        uint32_t boff = (uint32_t)(s & 1) * STG_B;
#pragma unroll
        for (int i = 0; i < 2; i++) {
            int ch = tid + i * 256;
            int r = ch >> 2, c = ch & 3;
            uint32_t doff = boff + (uint32_t)(r * 80 + c * 16);
            CPASYNC16(sA + doff, hin + (size_t)(m0 + r) * HH + k0 + c * 8);
            CPASYNC16(sB + doff, d_whh + (size_t)(n0 + r) * HH + k0 + c * 8);
        }
    };

    float acc[4][4][4];
#pragma unroll
    for (int i = 0; i < 4; i++)
#pragma unroll
        for (int j = 0; j < 4; j++)
#pragma unroll
            for (int q = 0; q < 4; q++) acc[i][j][q] = 0.f;

    issue(0);
    asm volatile("cp.async.commit_group;");
    issue(1);
    asm volatile("cp.async.commit_group;");

    int lrow = lane & 7, grp = lane >> 3;

    for (int s = 0; s < 20; s++) {
        asm volatile("cp.async.wait_group 1;" ::: "memory");
        __syncthreads();
        uint32_t boff = (uint32_t)(s & 1) * STG_B;

#pragma unroll
        for (int kk = 0; kk < 2; kk++) {
            uint32_t a_f[4][4];
#pragma unroll
            for (int mt = 0; mt < 4; mt++) {
                uint32_t ra = (uint32_t)(warp_m0 + mt * 16 + ((grp & 1) << 3) + lrow);
                uint32_t ca = (uint32_t)(kk * 16 + ((grp >> 1) << 3));
                ldmx4(a_f[mt], sA + boff + ra * 80 + ca * 2);
            }
            uint32_t b_f[4][2];
#pragma unroll
            for (int nt2 = 0; nt2 < 2; nt2++) {
                uint32_t rb = (uint32_t)(warp_n0 + nt2 * 16 + ((grp >> 1) << 3) + lrow);
                uint32_t cb = (uint32_t)(kk * 16 + ((grp & 1) << 3));
                uint32_t rh[4];
                ldmx4(rh, sB + boff + rb * 80 + cb * 2);
                b_f[nt2 * 2 + 0][0] = rh[0]; b_f[nt2 * 2 + 0][1] = rh[1];
                b_f[nt2 * 2 + 1][0] = rh[2]; b_f[nt2 * 2 + 1][1] = rh[3];
            }
#pragma unroll
            for (int mt = 0; mt < 4; mt++)
#pragma unroll
                for (int nt = 0; nt < 4; nt++)
                    mma16816(acc[mt][nt], a_f[mt], b_f[nt]);
        }
        __syncthreads();
        if (s + 2 < 20) issue(s + 2);
        asm volatile("cp.async.commit_group;");
    }

    int lrow4 = lane >> 2, lcol2 = (lane & 3) * 2;
#pragma unroll
    for (int mt = 0; mt < 4; mt++)
#pragma unroll
        for (int nt = 0; nt < 4; nt++) {
            int row = warp_m0 + mt * 16 + lrow4;
            int col = warp_n0 + nt * 8 + lcol2;
            *(float2*)&Csm[row * CST + col] = make_float2(acc[mt][nt][0], acc[mt][nt][1]);
            *(float2*)&Csm[(row + 8) * CST + col] = make_float2(acc[mt][nt][2], acc[mt][nt][3]);
        }
    __syncthreads();

    int half_ = tid >> 7;
    int ml = tid & 127;
    int m = m0 + ml;
    if (m < BB) {
        int tok = __ldg(&smi[m * TT + t]);
        int cb0 = half_ * 64;
        int chb = (n0 >> 2) + half_ * 16;
        const float* tokp = d_tok + (size_t)tok * G4 + n0 + cb0;
        const float* cp = &Csm[ml * CST + cb0];
        float* crow = d_cl + (size_t)m * HH + chb;
        __half* hhp = hout + (size_t)m * HH + chb;
        float* hfp = d_hl + (size_t)m * HH + chb;

#pragma unroll
        for (int q = 0; q < 4; q++) {
            float4 cold = *(const float4*)(crow + q * 4);
            float co[4] = {cold.x, cold.y, cold.z, cold.w};
            float cn[4], hv[4];
            alignas(8) __half hh4[4];
#pragma unroll
            for (int j = 0; j < 4; j++) {
                int u = q * 16 + j * 4;
                float gi = sigf(cp[u + 0] + tokp[u + 0]);
                float gf = sigf(cp[u + 1] + tokp[u + 1]);
                float gg = tanhf_fast(cp[u + 2] + tokp[u + 2]);
                float go = sigf(cp[u + 3] + tokp[u + 3]);
                float c = gf * co[j] + gi * gg;
                cn[j] = c;
                float h = go * tanhf_fast(c);
                hv[j] = h;
                hh4[j] = __float2half(h);
            }
            *(float4*)(crow + q * 4) = make_float4(cn[0], cn[1], cn[2], cn[3]);
            *(uint2*)(hhp + q * 4) = *(const uint2*)hh4;
            if (last)
                *(float4*)(hfp + q * 4) = make_float4(hv[0], hv[1], hv[2], hv[3]);
        }
    }
}

// ---------------- BatchNorm (training-mode batch stats) ----------------
__global__ void k_bnstat(const float* __restrict__ X, int M) {
    int c = threadIdx.x;
    int C = blockDim.x;
    float s = 0.f, q = 0.f;
    for (int r = blockIdx.x; r < M; r += gridDim.x) {
        float v = X[(size_t)r * C + c];
        s += v; q += v * v;
    }
    atomicAdd(&d_stat[c], s);
    atomicAdd(&d_stat[512 + c], q);
}

__global__ void k_bnfin(int M, int C) {
    int c = blockIdx.x * blockDim.x + threadIdx.x;
    if (c < C) {
        float mu = d_stat[c] / (float)M;
        float var = d_stat[512 + c] / (float)M - mu * mu;
        d_mu[c] = mu;
        d_rstd[c] = rsqrtf(var + 1e-5f);
    }
}

__global__ void k_bnpool(const float* __restrict__ Z, float* __restrict__ Hout,
                         const float* __restrict__ gamma, const float* __restrict__ beta,
                         const int* __restrict__ batch, int layer) {
    int idx = blockIdx.x * blockDim.x + threadIdx.x;
    if (idx >= NN * DD) return;
    int c = idx & 127, n = idx >> 7;
    float v = (Z[idx] - d_mu[c]) * d_rstd[c] * gamma[c] + beta[c];
    Hout[idx] = v;
    atomicAdd(&d_enc1[(size_t)batch[n] * HH + layer * DD + c], v);
}

__global__ void k_bnrelu(float* __restrict__ X, const float* __restrict__ gamma,
                         const float* __restrict__ beta, int M, int C) {
    int idx = blockIdx.x * blockDim.x + threadIdx.x;
    if (idx >= M * C) return;
    int c = idx % C;
    float v = (X[idx] - d_mu[c]) * d_rstd[c] * gamma[c] + beta[c];
    X[idx] = fmaxf(v, 0.f);
}

__global__ void k_l2(const float* __restrict__ X, float* __restrict__ out, int C) {
    __shared__ float red[256];
    int r = blockIdx.x;
    float s = 0.f;
    for (int c = threadIdx.x; c < C; c += 256) {
        float v = X[(size_t)r * C + c];
        s += v * v;
    }
    red[threadIdx.x] = s;
    __syncthreads();
    for (int off = 128; off > 0; off >>= 1) {
        if (threadIdx.x < off) red[threadIdx.x] += red[threadIdx.x + off];
        __syncthreads();
    }
    float inv = 1.f / fmaxf(sqrtf(red[0]), 1e-12f);
    for (int c = threadIdx.x; c < C; c += 256)
        out[(size_t)r * C + c] = X[(size_t)r * C + c] * inv;
}

// ---------------- host orchestration ----------------
static void* symaddr(const void* sym) {
    void* p = nullptr;
    cudaGetSymbolAddress(&p, sym);
    return p;
}

extern "C" void kernel_launch(void* const* d_in, const int* in_sizes, int n_in,
                              void* d_out, int out_size) {
    const float* x        = (const float*)d_in[0];
    const int*   ei       = (const int*)d_in[1];
    const int*   batch    = (const int*)d_in[2];
    const int*   smi      = (const int*)d_in[3];
    const float* gin0_w1  = (const float*)d_in[4];
    const float* gin0_b1  = (const float*)d_in[5];
    const float* gin0_w2  = (const float*)d_in[6];
    const float* gin0_b2  = (const float*)d_in[7];
    const float* ginr_w1  = (const float*)d_in[8];
    const float* ginr_b1  = (const float*)d_in[9];
    const float* ginr_w2  = (const float*)d_in[10];
    const float* ginr_b2  = (const float*)d_in[11];
    const float* bn_gamma = (const float*)d_in[12];
    const float* bn_beta  = (const float*)d_in[13];
    const float* emb      = (const float*)d_in[14];
    const float* w_ih     = (const float*)d_in[15];
    const float* w_hh     = (const float*)d_in[16];
    const float* b_ih     = (const float*)d_in[17];
    const float* b_hh     = (const float*)d_in[18];
    const float* g_w1     = (const float*)d_in[19];
    const float* g_b1     = (const float*)d_in[20];
    const float* g_bng    = (const float*)d_in[21];
    const float* g_bnb    = (const float*)d_in[22];
    const float* g_w2     = (const float*)d_in[23];
    float* out = (float*)d_out;

    const int* e_src = ei;
    const int* e_dst = ei + EE;

    float* p_h    = (float*)symaddr(d_h);
    float* p_z    = (float*)symaddr(d_z);
    float* p_enc1 = (float*)symaddr(d_enc1);
    float* p_hl   = (float*)symaddr(d_hl);
    float* p_cl   = (float*)symaddr(d_cl);
    float* p_proj = (float*)symaddr(d_proj);
    float* p_head = (float*)symaddr(d_head);
    float* p_stat = (float*)symaddr(d_stat);
    int*   p_deg  = (int*)symaddr(d_deg);
    __half* p_hh  = (__half*)symaddr(d_hh);
    __half* p_zh  = (__half*)symaddr(d_zh);
    __half* p_zl  = (__half*)symaddr(d_zl);
    __half* p_t1h = (__half*)symaddr(d_t1h);
    __half* p_t1l = (__half*)symaddr(d_t1l);

    // ---- CSR build ----
    cudaMemsetAsync(p_deg, 0, NN * sizeof(int));
    k_count<<<(EE + 255) / 256, 256>>>(e_dst);
    int nb = (NN + 1023) / 1024;
    k_scan1<<<nb, 1024>>>();
    k_scan2<<<1, 32>>>(nb);
    k_scan3<<<(NN + 255) / 256, 256>>>();
    k_fill<<<(EE + 255) / 256, 256>>>(e_src, e_dst);

    cudaMemsetAsync(p_enc1, 0, (size_t)BB * HH * sizeof(float));

    // ---- GIN layers (fp16x3 HMMA GEMMs) ----
    const int GSM = 8 * GSTG;   // 81920
    cudaFuncSetAttribute(k_gemm16, cudaFuncAttributeMaxDynamicSharedMemorySize, GSM);
    dim3 gg(1, NPAD / 128);     // (1, 782)

    for (int l = 0; l < LL; l++) {
        const float* hin = (l == 0) ? x : p_h;
        const float* w1 = (l == 0) ? gin0_w1 : ginr_w1 + (size_t)(l - 1) * DD * DD;
        const float* b1 = (l == 0) ? gin0_b1 : ginr_b1 + (size_t)(l - 1) * DD;
        const float* w2 = (l == 0) ? gin0_w2 : ginr_w2 + (size_t)(l - 1) * DD * DD;
        const float* b2 = (l == 0) ? gin0_b2 : ginr_b2 + (size_t)(l - 1) * DD;
        int K1 = (l == 0) ? FIN : DD;

        if (l == 0)
            k_gather16<8><<<(NN * 8 + 255) / 256, 256>>>(hin, p_zh, p_zl);
        else
            k_gather16<32><<<(NN * 32 + 255) / 256, 256>>>(hin, p_zh, p_zl);

        k_wt16<<<(128 * K1 + 255) / 256, 256>>>(w1, K1);
        k_gemm16<<<gg, 256, GSM>>>(p_zh, p_zl, b1, p_t1h, p_t1l, nullptr, K1);
        k_wt16<<<(128 * 128 + 255) / 256, 256>>>(w2, 128);
        k_gemm16<<<gg, 256, GSM>>>(p_t1h, p_t1l, b2, nullptr, nullptr, p_z, 128);

        cudaMemsetAsync(p_stat, 0, 1024 * sizeof(float));
        k_bnstat<<<512, DD>>>(p_z, NN);
        k_bnfin<<<1, DD>>>(NN, DD);
        k_bnpool<<<(NN * DD + 255) / 256, 256>>>(p_z, p_h, bn_gamma + l * DD,
                                                 bn_beta + l * DD, batch, l);
    }

    // ---- LSTM (mma.sync fp16 single-pass, fused update, ping-pong h) ----
    k_tok<<<(VV * G4 + 255) / 256, 256>>>(emb, w_ih, b_ih, b_hh);
    k_whh_split<<<(G4 * HH + 255) / 256, 256>>>(w_hh);
    cudaMemsetAsync(p_hh, 0, (size_t)2 * MPAD * HH * sizeof(__half));
    cudaMemsetAsync(p_cl, 0, (size_t)BB * HH * sizeof(float));

    const int DSMEM = 128 * CST * 4;               // 67584 >= 4*STG_B (40960)
    cudaFuncSetAttribute(k_lstm_step, cudaFuncAttributeMaxDynamicSharedMemorySize, DSMEM);
    dim3 gl(G4 / 128, MPAD / 128);                 // (20, 24)
    const size_t HBUF = (size_t)MPAD * HH;
    for (int t = 0; t < TT; t++) {
        int cur = t & 1, nxt = (t + 1) & 1;
        k_lstm_step<<<gl, 256, DSMEM>>>(smi,
            p_hh + cur * HBUF, p_hh + nxt * HBUF,
            t, (t == TT - 1) ? 1 : 0);
    }

    // ---- heads ----
    for (int which = 0; which < 2; which++) {
        const float* src = (which == 0) ? p_enc1 : p_hl;
        float* dst = out + (size_t)which * BB * 768;

        dim3 gp(512 / 128, (BB + 127) / 128);
        k_gemm<<<gp, 256>>>(src, g_w1, g_b1, p_proj, BB, 512, HH, 0);

        cudaMemsetAsync(p_stat, 0, 1024 * sizeof(float));
        k_bnstat<<<256, 512>>>(p_proj, BB);
        k_bnfin<<<2, 256>>>(BB, 512);
        k_bnrelu<<<(BB * 512 + 255) / 256, 256>>>(p_proj, g_bng, g_bnb, BB, 512);

        dim3 go(768 / 128, (BB + 127) / 128);
        k_gemm<<<go, 256>>>(p_proj, g_w2, nullptr, p_head, BB, 768, 512, 0);

        k_l2<<<BB, 256>>>(p_head, dst, 768);
    }
}

// round 11
// speedup vs baseline: 1.0038x; 1.0038x over previous
#include <cuda_runtime.h>
#include <cuda_fp16.h>
#include <cstdint>

#define NN 100000
#define NPAD 100096   // 782 * 128
#define EE 1600000
#define FIN 32
#define DD 128
#define LL 5
#define BB 3000
#define VV 64
#define TT 128
#define EMBD 64
#define HH 640      // L*D LSTM hidden
#define G4 2560     // 4*H
#define MPAD 3072   // 24 * 128

// ---------------- scratch (device globals; no allocation allowed) ----------------
__device__ float d_h[NN * DD];
__device__ float d_z[NN * DD];
__device__ int   d_deg[NN];
__device__ int   d_rowptr[NN + 1];
__device__ int   d_cursor[NN];
__device__ int   d_col[EE];
__device__ int   d_bsum[256];
__device__ float d_stat[1024];
__device__ float d_mu[512];
__device__ float d_rstd[512];
__device__ float d_enc1[BB * HH];
__device__ float d_tok[VV * G4];          // interleaved: col j = ch*4+gate
__device__ float d_hl[BB * HH];
__device__ float d_cl[BB * HH];
__device__ float d_proj[BB * 512];
__device__ float d_head[BB * 768];
__device__ __half d_whh[G4 * HH];         // fp16-rounded Whh (interleaved rows, K-major)
__device__ __half d_hh[2 * MPAD * HH];    // ping-pong h (read t&1, write (t+1)&1)
// GIN fp16 scratch (padded rows stay zero)
__device__ __half d_zh[NPAD * DD];
__device__ __half d_zl[NPAD * DD];
__device__ __half d_t1h[NPAD * DD];
__device__ __half d_t1l[NPAD * DD];
__device__ __half d_wth[DD * DD];         // W^T hi  [N=128, K]
__device__ __half d_wtl[DD * DD];         // W^T lo

// ================= PTX helpers (compute_100-safe: cp.async / ldmatrix / mma.sync) ======
__device__ __forceinline__ uint32_t smem_u32(const void* p) {
    uint32_t a;
    asm("{ .reg .u64 t; cvta.to.shared.u64 t, %1; cvt.u32.u64 %0, t; }" : "=r"(a) : "l"(p));
    return a;
}

#define CPASYNC16(dst, src) \
    asm volatile("cp.async.cg.shared.global [%0], [%1], 16;" :: "r"(dst), "l"(src))

__device__ __forceinline__ void ldmx4(uint32_t* r, uint32_t addr) {
    asm volatile("ldmatrix.sync.aligned.m8n8.x4.shared.b16 {%0,%1,%2,%3}, [%4];"
        : "=r"(r[0]), "=r"(r[1]), "=r"(r[2]), "=r"(r[3]) : "r"(addr));
}

__device__ __forceinline__ void mma16816(float* c, const uint32_t* a, const uint32_t* b) {
    asm volatile("mma.sync.aligned.m16n8k16.row.col.f32.f16.f16.f32 "
        "{%0,%1,%2,%3}, {%4,%5,%6,%7}, {%8,%9}, {%0,%1,%2,%3};"
        : "+f"(c[0]), "+f"(c[1]), "+f"(c[2]), "+f"(c[3])
        : "r"(a[0]), "r"(a[1]), "r"(a[2]), "r"(a[3]), "r"(b[0]), "r"(b[1]));
}

// ---------------- CSR build ----------------
__global__ void k_count(const int* __restrict__ dst) {
    int e = blockIdx.x * blockDim.x + threadIdx.x;
    if (e < EE) atomicAdd(&d_deg[dst[e]], 1);
}

__global__ void k_scan1() {
    __shared__ int s[1024];
    int i = blockIdx.x * 1024 + threadIdx.x;
    int v = (i < NN) ? d_deg[i] : 0;
    s[threadIdx.x] = v;
    __syncthreads();
    for (int off = 1; off < 1024; off <<= 1) {
        int t = (threadIdx.x >= off) ? s[threadIdx.x - off] : 0;
        __syncthreads();
        s[threadIdx.x] += t;
        __syncthreads();
    }
    if (i < NN) d_rowptr[i] = s[threadIdx.x];
    if (threadIdx.x == 1023) d_bsum[blockIdx.x] = s[1023];
}

__global__ void k_scan2(int nb) {
    if (threadIdx.x == 0 && blockIdx.x == 0) {
        int acc = 0;
        for (int i = 0; i < nb; i++) { int v = d_bsum[i]; d_bsum[i] = acc; acc += v; }
    }
}

__global__ void k_scan3() {
    int i = blockIdx.x * blockDim.x + threadIdx.x;
    if (i < NN) {
        int start = d_rowptr[i] + d_bsum[i >> 10] - d_deg[i];
        d_rowptr[i] = start;
        d_cursor[i] = start;
        if (i == 0) d_rowptr[NN] = EE;
    }
}

__global__ void k_fill(const int* __restrict__ src, const int* __restrict__ dst) {
    int e = blockIdx.x * blockDim.x + threadIdx.x;
    if (e < EE) {
        int p = atomicAdd(&d_cursor[dst[e]], 1);
        d_col[p] = src[e];
    }
}

// ---------------- GIN gather: z = h + sum_{j->i} h_j, emitted as fp16 hi/lo ----------
template <int D4P>
__global__ void k_gather16(const float* __restrict__ hin,
                           __half* __restrict__ zh, __half* __restrict__ zl) {
    int idx = blockIdx.x * blockDim.x + threadIdx.x;
    if (idx >= NN * D4P) return;
    int n = idx / D4P, c = idx % D4P;
    const float4* H = (const float4*)hin;
    float4 a = H[(size_t)n * D4P + c];
    int p1 = d_rowptr[n + 1];
    for (int p = d_rowptr[n]; p < p1; p++) {
        int s = d_col[p];
        float4 b = __ldg(&H[(size_t)s * D4P + c]);
        a.x += b.x; a.y += b.y; a.z += b.z; a.w += b.w;
    }
    alignas(8) __half h4[4], l4[4];
    float v[4] = {a.x, a.y, a.z, a.w};
#pragma unroll
    for (int j = 0; j < 4; j++) {
        __half hi = __float2half(v[j]);
        h4[j] = hi;
        l4[j] = __float2half(v[j] - __half2float(hi));
    }
    ((uint2*)zh)[idx] = *(const uint2*)h4;
    ((uint2*)zl)[idx] = *(const uint2*)l4;
}

// ---------------- weight transpose + exact fp16 hi/lo split: W[K,128] -> wt[128,K] ----
__global__ void k_wt16(const float* __restrict__ W, int K) {
    int idx = blockIdx.x * blockDim.x + threadIdx.x;
    if (idx >= 128 * K) return;
    int n = idx / K, k = idx % K;
    float v = W[(size_t)k * 128 + n];
    __half hi = __float2half(v);
    d_wth[idx] = hi;
    d_wtl[idx] = __float2half(v - __half2float(hi));
}

// ---------------- GIN fp16x3 GEMM: out = relu(A[M,K] @ Wt^T + bias), N=128 -----------
// grid (1, 782), 256 thr, 8 warps (2x4). CTA tile M=128, N=128. 3 mma passes.
#define GSTG 10240      // one stage buffer: 128 rows x 80B (32 fp16 + 8 pad)

__global__ __launch_bounds__(256, 1) void k_gemm16(
    const __half* __restrict__ Ah, const __half* __restrict__ Al,
    const float* __restrict__ bias,
    __half* __restrict__ outh, __half* __restrict__ outl,
    float* __restrict__ outf, int K)
{
    extern __shared__ char dsm[];
    uint32_t sb = smem_u32(dsm);
    int nk = K / 32;
    int tid = threadIdx.x;
    int warp = tid >> 5, lane = tid & 31;
    int m0 = blockIdx.y * 128;
    int warp_m0 = (warp >> 2) * 64, warp_n0 = (warp & 3) * 32;

    // slot layout: [slot*40960): Ah +0, Al +10240, Bh +20480, Bl +30720
    auto issue = [&](int s) {
        if (s >= nk) return;
        int k0 = s * 32;
        uint32_t base = sb + (uint32_t)(s & 1) * 4 * GSTG;
#pragma unroll
        for (int i = 0; i < 2; i++) {
            int ch = tid + i * 256;
            int r = ch >> 3, c = ch & 7;  // wrong split for 512? careful below
            (void)r; (void)c;
        }
        // A: 128 rows x 4 chunks of 16B
#pragma unroll
        for (int i = 0; i < 2; i++) {
            int ch = tid + i * 256;       // 0..511
            int r = ch >> 2, c = ch & 3;
            uint32_t doff = (uint32_t)(r * 80 + c * 16);
            CPASYNC16(base + doff, Ah + (size_t)(m0 + r) * K + k0 + c * 8);
            CPASYNC16(base + 10240 + doff, Al + (size_t)(m0 + r) * K + k0 + c * 8);
            CPASYNC16(base + 20480 + doff, d_wth + (size_t)r * K + k0 + c * 8);
            CPASYNC16(base + 30720 + doff, d_wtl + (size_t)r * K + k0 + c * 8);
        }
    };

    float acc[4][4][4];
#pragma unroll
    for (int i = 0; i < 4; i++)
#pragma unroll
        for (int j = 0; j < 4; j++)
#pragma unroll
            for (int q = 0; q < 4; q++) acc[i][j][q] = 0.f;

    issue(0);
    asm volatile("cp.async.commit_group;");
    issue(1);
    asm volatile("cp.async.commit_group;");

    int lrow = lane & 7, grp = lane >> 3;

    for (int s = 0; s < nk; s++) {
        asm volatile("cp.async.wait_group 1;" ::: "memory");
        __syncthreads();
        uint32_t base = sb + (uint32_t)(s & 1) * 4 * GSTG;
        uint32_t sAh = base, sAl = base + 10240, sBh = base + 20480, sBl = base + 30720;

#pragma unroll
        for (int kk = 0; kk < 2; kk++) {
            uint32_t a_hi[4][4], a_lo[4][4];
#pragma unroll
            for (int mt = 0; mt < 4; mt++) {
                uint32_t ra = (uint32_t)(warp_m0 + mt * 16 + ((grp & 1) << 3) + lrow);
                uint32_t ca = (uint32_t)(kk * 16 + ((grp >> 1) << 3));
                uint32_t off = ra * 80 + ca * 2;
                ldmx4(a_hi[mt], sAh + off);
                ldmx4(a_lo[mt], sAl + off);
            }
            uint32_t b_hi[4][2], b_lo[4][2];
#pragma unroll
            for (int nt2 = 0; nt2 < 2; nt2++) {
                uint32_t rb = (uint32_t)(warp_n0 + nt2 * 16 + ((grp >> 1) << 3) + lrow);
                uint32_t cb = (uint32_t)(kk * 16 + ((grp & 1) << 3));
                uint32_t off = rb * 80 + cb * 2;
                uint32_t rh[4], rl[4];
                ldmx4(rh, sBh + off);
                ldmx4(rl, sBl + off);
                b_hi[nt2 * 2 + 0][0] = rh[0]; b_hi[nt2 * 2 + 0][1] = rh[1];
                b_hi[nt2 * 2 + 1][0] = rh[2]; b_hi[nt2 * 2 + 1][1] = rh[3];
                b_lo[nt2 * 2 + 0][0] = rl[0]; b_lo[nt2 * 2 + 0][1] = rl[1];
                b_lo[nt2 * 2 + 1][0] = rl[2]; b_lo[nt2 * 2 + 1][1] = rl[3];
            }
#pragma unroll
            for (int mt = 0; mt < 4; mt++)
#pragma unroll
                for (int nt = 0; nt < 4; nt++) {
                    mma16816(acc[mt][nt], a_hi[mt], b_hi[nt]);
                    mma16816(acc[mt][nt], a_hi[mt], b_lo[nt]);
                    mma16816(acc[mt][nt], a_lo[mt], b_hi[nt]);
                }
        }
        __syncthreads();
        issue(s + 2);
        asm volatile("cp.async.commit_group;");
    }

    // ---- epilogue: bias + relu, direct register -> global ----
    int lrow4 = lane >> 2, lcol2 = (lane & 3) * 2;
#pragma unroll
    for (int mt = 0; mt < 4; mt++)
#pragma unroll
        for (int nt = 0; nt < 4; nt++) {
            int col = warp_n0 + nt * 8 + lcol2;
            float b0 = __ldg(&bias[col]), b1v = __ldg(&bias[col + 1]);
#pragma unroll
            for (int hr = 0; hr < 2; hr++) {
                int m = m0 + warp_m0 + mt * 16 + lrow4 + hr * 8;
                if (m >= NN) continue;
                float v0 = fmaxf(acc[mt][nt][hr * 2 + 0] + b0, 0.f);
                float v1 = fmaxf(acc[mt][nt][hr * 2 + 1] + b1v, 0.f);
                if (outf) {
                    *(float2*)(outf + (size_t)m * 128 + col) = make_float2(v0, v1);
                } else {
                    __half h0 = __float2half(v0), h1 = __float2half(v1);
                    __half l0 = __float2half(v0 - __half2float(h0));
                    __half l1 = __float2half(v1 - __half2float(h1));
                    alignas(4) __half hp[2] = {h0, h1}, lp[2] = {l0, l1};
                    *(uint32_t*)(outh + (size_t)m * 128 + col) = *(const uint32_t*)hp;
                    *(uint32_t*)(outl + (size_t)m * 128 + col) = *(const uint32_t*)lp;
                }
            }
        }
}

// ---------------- Generic fp32 GEMM (heads): C = act(A[M,K] @ W[K,N] + bias) ---------
__global__ __launch_bounds__(256) void k_gemm(const float* __restrict__ A,
                                              const float* __restrict__ W,
                                              const float* __restrict__ bias,
                                              float* __restrict__ C,
                                              int M, int N, int K, int relu) {
    __shared__ float As[16][132];
    __shared__ float Bs[16][132];
    int tid = threadIdx.x;
    int m0 = blockIdx.y * 128, n0 = blockIdx.x * 128;
    int ty = tid >> 4, tx = tid & 15;
    float acc[8][8];
#pragma unroll
    for (int i = 0; i < 8; i++)
#pragma unroll
        for (int j = 0; j < 8; j++) acc[i][j] = 0.f;

    for (int k0 = 0; k0 < K; k0 += 16) {
#pragma unroll
        for (int i = 0; i < 2; i++) {
            int lin = tid + i * 256;
            int r = lin >> 2, c4 = lin & 3;
            float4 v = make_float4(0.f, 0.f, 0.f, 0.f);
            if (m0 + r < M) v = *(const float4*)(A + (size_t)(m0 + r) * K + k0 + c4 * 4);
            As[c4 * 4 + 0][r] = v.x; As[c4 * 4 + 1][r] = v.y;
            As[c4 * 4 + 2][r] = v.z; As[c4 * 4 + 3][r] = v.w;
        }
#pragma unroll
        for (int i = 0; i < 2; i++) {
            int lin = tid + i * 256;
            int kk = lin >> 5, n4 = lin & 31;
            float4 v = *(const float4*)(W + (size_t)(k0 + kk) * N + n0 + n4 * 4);
            *(float4*)&Bs[kk][n4 * 4] = v;
        }
        __syncthreads();
#pragma unroll
        for (int k = 0; k < 16; k++) {
            float4 a0 = *(const float4*)&As[k][ty * 4];
            float4 a1 = *(const float4*)&As[k][64 + ty * 4];
            float4 b0 = *(const float4*)&Bs[k][tx * 4];
            float4 b1 = *(const float4*)&Bs[k][64 + tx * 4];
            float a[8] = {a0.x, a0.y, a0.z, a0.w, a1.x, a1.y, a1.z, a1.w};
            float b[8] = {b0.x, b0.y, b0.z, b0.w, b1.x, b1.y, b1.z, b1.w};
#pragma unroll
            for (int i = 0; i < 8; i++)
#pragma unroll
                for (int j = 0; j < 8; j++) acc[i][j] += a[i] * b[j];
        }
        __syncthreads();
    }
#pragma unroll
    for (int i = 0; i < 8; i++) {
        int m = m0 + ((i < 4) ? ty * 4 + i : 64 + ty * 4 + (i - 4));
        if (m >= M) continue;
#pragma unroll
        for (int j = 0; j < 8; j++) {
            int n = n0 + ((j < 4) ? tx * 4 + j : 64 + tx * 4 + (j - 4));
            float v = acc[i][j];
            if (bias) v += __ldg(&bias[n]);
            if (relu) v = fmaxf(v, 0.f);
            C[(size_t)m * N + n] = v;
        }
    }
}

// ---------------- prep: interleaved fp16-rounded Whh ----------------
__global__ void k_whh_split(const float* __restrict__ whh) {
    int idx = blockIdx.x * blockDim.x + threadIdx.x;
    if (idx >= G4 * HH) return;
    int j = idx / HH, k = idx % HH;
    int gate = j & 3, ch = j >> 2;
    d_whh[idx] = __float2half(whh[(size_t)(gate * HH + ch) * HH + k]);
}

// token gate table, gate-interleaved columns: j = ch*4+gate
__global__ void k_tok(const float* __restrict__ emb, const float* __restrict__ wih,
                      const float* __restrict__ bih, const float* __restrict__ bhh) {
    int idx = blockIdx.x * blockDim.x + threadIdx.x;
    if (idx >= VV * G4) return;
    int v = idx / G4, j = idx % G4;
    int row = (j & 3) * HH + (j >> 2);
    float s = bih[row] + bhh[row];
#pragma unroll 16
    for (int k = 0; k < EMBD; k++) s += emb[v * EMBD + k] * wih[row * EMBD + k];
    d_tok[idx] = s;
}

__device__ __forceinline__ float sigf(float x) {
    return __fdividef(1.f, 1.f + __expf(-x));
}
__device__ __forceinline__ float tanhf_fast(float x) {
    return 1.f - __fdividef(2.f, __expf(2.f * x) + 1.f);
}

// ---------------- fused LSTM step (R7 config): mma.sync fp16 + gate update ------------
// grid (20, 24), 256 threads (8 warps, 2x4). CTA tile: M=128 rows, N=128 cols
#define STG_B 10240
#define CST 132

__global__ __launch_bounds__(256, 2) void k_lstm_step(
    const int* __restrict__ smi,
    const __half* __restrict__ hin,
    __half* __restrict__ hout,
    int t, int last)
{
    extern __shared__ char dsm[];
    uint32_t sb = smem_u32(dsm);
    uint32_t sA = sb, sB = sb + 2 * STG_B;
    float* Csm = (float*)dsm;

    int tid = threadIdx.x;
    int warp = tid >> 5, lane = tid & 31;
    int m0 = blockIdx.y * 128, n0 = blockIdx.x * 128;
    int warp_m0 = (warp >> 2) * 64, warp_n0 = (warp & 3) * 32;

    auto issue = [&](int s) {
        int k0 = s * 32;
        uint32_t boff = (uint32_t)(s & 1) * STG_B;
#pragma unroll
        for (int i = 0; i < 2; i++) {
            int ch = tid + i * 256;
            int r = ch >> 2, c = ch & 3;
            uint32_t doff = boff + (uint32_t)(r * 80 + c * 16);
            CPASYNC16(sA + doff, hin + (size_t)(m0 + r) * HH + k0 + c * 8);
            CPASYNC16(sB + doff, d_whh + (size_t)(n0 + r) * HH + k0 + c * 8);
        }
    };

    float acc[4][4][4];
#pragma unroll
    for (int i = 0; i < 4; i++)
#pragma unroll
        for (int j = 0; j < 4; j++)
#pragma unroll
            for (int q = 0; q < 4; q++) acc[i][j][q] = 0.f;

    issue(0);
    asm volatile("cp.async.commit_group;");
    issue(1);
    asm volatile("cp.async.commit_group;");

    int lrow = lane & 7, grp = lane >> 3;

    for (int s = 0; s < 20; s++) {
        asm volatile("cp.async.wait_group 1;" ::: "memory");
        __syncthreads();
        uint32_t boff = (uint32_t)(s & 1) * STG_B;

#pragma unroll
        for (int kk = 0; kk < 2; kk++) {
            uint32_t a_f[4][4];
#pragma unroll
            for (int mt = 0; mt < 4; mt++) {
                uint32_t ra = (uint32_t)(warp_m0 + mt * 16 + ((grp & 1) << 3) + lrow);
                uint32_t ca = (uint32_t)(kk * 16 + ((grp >> 1) << 3));
                ldmx4(a_f[mt], sA + boff + ra * 80 + ca * 2);
            }
            uint32_t b_f[4][2];
#pragma unroll
            for (int nt2 = 0; nt2 < 2; nt2++) {
                uint32_t rb = (uint32_t)(warp_n0 + nt2 * 16 + ((grp >> 1) << 3) + lrow);
                uint32_t cb = (uint32_t)(kk * 16 + ((grp & 1) << 3));
                uint32_t rh[4];
                ldmx4(rh, sB + boff + rb * 80 + cb * 2);
                b_f[nt2 * 2 + 0][0] = rh[0]; b_f[nt2 * 2 + 0][1] = rh[1];
                b_f[nt2 * 2 + 1][0] = rh[2]; b_f[nt2 * 2 + 1][1] = rh[3];
            }
#pragma unroll
            for (int mt = 0; mt < 4; mt++)
#pragma unroll
                for (int nt = 0; nt < 4; nt++)
                    mma16816(acc[mt][nt], a_f[mt], b_f[nt]);
        }
        __syncthreads();
        if (s + 2 < 20) issue(s + 2);
        asm volatile("cp.async.commit_group;");
    }

    int lrow4 = lane >> 2, lcol2 = (lane & 3) * 2;
#pragma unroll
    for (int mt = 0; mt < 4; mt++)
#pragma unroll
        for (int nt = 0; nt < 4; nt++) {
            int row = warp_m0 + mt * 16 + lrow4;
            int col = warp_n0 + nt * 8 + lcol2;
            *(float2*)&Csm[row * CST + col] = make_float2(acc[mt][nt][0], acc[mt][nt][1]);
            *(float2*)&Csm[(row + 8) * CST + col] = make_float2(acc[mt][nt][2], acc[mt][nt][3]);
        }
    __syncthreads();

    int half_ = tid >> 7;
    int ml = tid & 127;
    int m = m0 + ml;
    if (m < BB) {
        int tok = __ldg(&smi[m * TT + t]);
        int cb0 = half_ * 64;
        int chb = (n0 >> 2) + half_ * 16;
        const float* tokp = d_tok + (size_t)tok * G4 + n0 + cb0;
        const float* cp = &Csm[ml * CST + cb0];
        float* crow = d_cl + (size_t)m * HH + chb;
        __half* hhp = hout + (size_t)m * HH + chb;
        float* hfp = d_hl + (size_t)m * HH + chb;

#pragma unroll
        for (int q = 0; q < 4; q++) {
            float4 cold = *(const float4*)(crow + q * 4);
            float co[4] = {cold.x, cold.y, cold.z, cold.w};
            float cn[4], hv[4];
            alignas(8) __half hh4[4];
#pragma unroll
            for (int j = 0; j < 4; j++) {
                int u = q * 16 + j * 4;
                float gi = sigf(cp[u + 0] + tokp[u + 0]);
                float gf = sigf(cp[u + 1] + tokp[u + 1]);
                float gg = tanhf_fast(cp[u + 2] + tokp[u + 2]);
                float go = sigf(cp[u + 3] + tokp[u + 3]);
                float c = gf * co[j] + gi * gg;
                cn[j] = c;
                float h = go * tanhf_fast(c);
                hv[j] = h;
                hh4[j] = __float2half(h);
            }
            *(float4*)(crow + q * 4) = make_float4(cn[0], cn[1], cn[2], cn[3]);
            *(uint2*)(hhp + q * 4) = *(const uint2*)hh4;
            if (last)
                *(float4*)(hfp + q * 4) = make_float4(hv[0], hv[1], hv[2], hv[3]);
        }
    }
}

// ---------------- BatchNorm (training-mode batch stats) ----------------
__global__ void k_bnstat(const float* __restrict__ X, int M) {
    int c = threadIdx.x;
    int C = blockDim.x;
    float s = 0.f, q = 0.f;
    for (int r = blockIdx.x; r < M; r += gridDim.x) {
        float v = X[(size_t)r * C + c];
        s += v; q += v * v;
    }
    atomicAdd(&d_stat[c], s);
    atomicAdd(&d_stat[512 + c], q);
}

__global__ void k_bnfin(int M, int C) {
    int c = blockIdx.x * blockDim.x + threadIdx.x;
    if (c < C) {
        float mu = d_stat[c] / (float)M;
        float var = d_stat[512 + c] / (float)M - mu * mu;
        d_mu[c] = mu;
        d_rstd[c] = rsqrtf(var + 1e-5f);
    }
}

__global__ void k_bnpool(const float* __restrict__ Z, float* __restrict__ Hout,
                         const float* __restrict__ gamma, const float* __restrict__ beta,
                         const int* __restrict__ batch, int layer) {
    int idx = blockIdx.x * blockDim.x + threadIdx.x;
    if (idx >= NN * DD) return;
    int c = idx & 127, n = idx >> 7;
    float v = (Z[idx] - d_mu[c]) * d_rstd[c] * gamma[c] + beta[c];
    Hout[idx] = v;
    atomicAdd(&d_enc1[(size_t)batch[n] * HH + layer * DD + c], v);
}

__global__ void k_bnrelu(float* __restrict__ X, const float* __restrict__ gamma,
                         const float* __restrict__ beta, int M, int C) {
    int idx = blockIdx.x * blockDim.x + threadIdx.x;
    if (idx >= M * C) return;
    int c = idx % C;
    float v = (X[idx] - d_mu[c]) * d_rstd[c] * gamma[c] + beta[c];
    X[idx] = fmaxf(v, 0.f);
}

__global__ void k_l2(const float* __restrict__ X, float* __restrict__ out, int C) {
    __shared__ float red[256];
    int r = blockIdx.x;
    float s = 0.f;
    for (int c = threadIdx.x; c < C; c += 256) {
        float v = X[(size_t)r * C + c];
        s += v * v;
    }
    red[threadIdx.x] = s;
    __syncthreads();
    for (int off = 128; off > 0; off >>= 1) {
        if (threadIdx.x < off) red[threadIdx.x] += red[threadIdx.x + off];
        __syncthreads();
    }
    float inv = 1.f / fmaxf(sqrtf(red[0]), 1e-12f);
    for (int c = threadIdx.x; c < C; c += 256)
        out[(size_t)r * C + c] = X[(size_t)r * C + c] * inv;
}

// ---------------- host orchestration ----------------
static void* symaddr(const void* sym) {
    void* p = nullptr;
    cudaGetSymbolAddress(&p, sym);
    return p;
}

extern "C" void kernel_launch(void* const* d_in, const int* in_sizes, int n_in,
                              void* d_out, int out_size) {
    const float* x        = (const float*)d_in[0];
    const int*   ei       = (const int*)d_in[1];
    const int*   batch    = (const int*)d_in[2];
    const int*   smi      = (const int*)d_in[3];
    const float* gin0_w1  = (const float*)d_in[4];
    const float* gin0_b1  = (const float*)d_in[5];
    const float* gin0_w2  = (const float*)d_in[6];
    const float* gin0_b2  = (const float*)d_in[7];
    const float* ginr_w1  = (const float*)d_in[8];
    const float* ginr_b1  = (const float*)d_in[9];
    const float* ginr_w2  = (const float*)d_in[10];
    const float* ginr_b2  = (const float*)d_in[11];
    const float* bn_gamma = (const float*)d_in[12];
    const float* bn_beta  = (const float*)d_in[13];
    const float* emb      = (const float*)d_in[14];
    const float* w_ih     = (const float*)d_in[15];
    const float* w_hh     = (const float*)d_in[16];
    const float* b_ih     = (const float*)d_in[17];
    const float* b_hh     = (const float*)d_in[18];
    const float* g_w1     = (const float*)d_in[19];
    const float* g_b1     = (const float*)d_in[20];
    const float* g_bng    = (const float*)d_in[21];
    const float* g_bnb    = (const float*)d_in[22];
    const float* g_w2     = (const float*)d_in[23];
    float* out = (float*)d_out;

    const int* e_src = ei;
    const int* e_dst = ei + EE;

    float* p_h    = (float*)symaddr(d_h);
    float* p_z    = (float*)symaddr(d_z);
    float* p_enc1 = (float*)symaddr(d_enc1);
    float* p_hl   = (float*)symaddr(d_hl);
    float* p_cl   = (float*)symaddr(d_cl);
    float* p_proj = (float*)symaddr(d_proj);
    float* p_head = (float*)symaddr(d_head);
    float* p_stat = (float*)symaddr(d_stat);
    int*   p_deg  = (int*)symaddr(d_deg);
    __half* p_hh  = (__half*)symaddr(d_hh);
    __half* p_zh  = (__half*)symaddr(d_zh);
    __half* p_zl  = (__half*)symaddr(d_zl);
    __half* p_t1h = (__half*)symaddr(d_t1h);
    __half* p_t1l = (__half*)symaddr(d_t1l);

    // ---- CSR build ----
    cudaMemsetAsync(p_deg, 0, NN * sizeof(int));
    k_count<<<(EE + 255) / 256, 256>>>(e_dst);
    int nb = (NN + 1023) / 1024;
    k_scan1<<<nb, 1024>>>();
    k_scan2<<<1, 32>>>(nb);
    k_scan3<<<(NN + 255) / 256, 256>>>();
    k_fill<<<(EE + 255) / 256, 256>>>(e_src, e_dst);

    cudaMemsetAsync(p_enc1, 0, (size_t)BB * HH * sizeof(float));

    // ---- GIN layers (fp16x3 HMMA GEMMs) ----
    const int GSM = 8 * GSTG;   // 81920
    cudaFuncSetAttribute(k_gemm16, cudaFuncAttributeMaxDynamicSharedMemorySize, GSM);
    dim3 gg(1, NPAD / 128);     // (1, 782)

    for (int l = 0; l < LL; l++) {
        const float* hin = (l == 0) ? x : p_h;
        const float* w1 = (l == 0) ? gin0_w1 : ginr_w1 + (size_t)(l - 1) * DD * DD;
        const float* b1 = (l == 0) ? gin0_b1 : ginr_b1 + (size_t)(l - 1) * DD;
        const float* w2 = (l == 0) ? gin0_w2 : ginr_w2 + (size_t)(l - 1) * DD * DD;
        const float* b2 = (l == 0) ? gin0_b2 : ginr_b2 + (size_t)(l - 1) * DD;
        int K1 = (l == 0) ? FIN : DD;

        if (l == 0)
            k_gather16<8><<<(NN * 8 + 255) / 256, 256>>>(hin, p_zh, p_zl);
        else
            k_gather16<32><<<(NN * 32 + 255) / 256, 256>>>(hin, p_zh, p_zl);

        k_wt16<<<(128 * K1 + 255) / 256, 256>>>(w1, K1);
        k_gemm16<<<gg, 256, GSM>>>(p_zh, p_zl, b1, p_t1h, p_t1l, nullptr, K1);
        k_wt16<<<(128 * 128 + 255) / 256, 256>>>(w2, 128);
        k_gemm16<<<gg, 256, GSM>>>(p_t1h, p_t1l, b2, nullptr, nullptr, p_z, 128);

        cudaMemsetAsync(p_stat, 0, 1024 * sizeof(float));
        k_bnstat<<<512, DD>>>(p_z, NN);
        k_bnfin<<<1, DD>>>(NN, DD);
        k_bnpool<<<(NN * DD + 255) / 256, 256>>>(p_z, p_h, bn_gamma + l * DD,
                                                 bn_beta + l * DD, batch, l);
    }

    // ---- LSTM (mma.sync fp16 single-pass, fused update, ping-pong h) ----
    k_tok<<<(VV * G4 + 255) / 256, 256>>>(emb, w_ih, b_ih, b_hh);
    k_whh_split<<<(G4 * HH + 255) / 256, 256>>>(w_hh);
    cudaMemsetAsync(p_hh, 0, (size_t)2 * MPAD * HH * sizeof(__half));
    cudaMemsetAsync(p_cl, 0, (size_t)BB * HH * sizeof(float));

    const int DSMEM = 128 * CST * 4;               // 67584 >= 4*STG_B (40960)
    cudaFuncSetAttribute(k_lstm_step, cudaFuncAttributeMaxDynamicSharedMemorySize, DSMEM);
    dim3 gl(G4 / 128, MPAD / 128);                 // (20, 24)
    const size_t HBUF = (size_t)MPAD * HH;
    for (int t = 0; t < TT; t++) {
        int cur = t & 1, nxt = (t + 1) & 1;
        k_lstm_step<<<gl, 256, DSMEM>>>(smi,
            p_hh + cur * HBUF, p_hh + nxt * HBUF,
            t, (t == TT - 1) ? 1 : 0);
    }

    // ---- heads ----
    for (int which = 0; which < 2; which++) {
        const float* src = (which == 0) ? p_enc1 : p_hl;
        float* dst = out + (size_t)which * BB * 768;

        dim3 gp(512 / 128, (BB + 127) / 128);
        k_gemm<<<gp, 256>>>(src, g_w1, g_b1, p_proj, BB, 512, HH, 0);

        cudaMemsetAsync(p_stat, 0, 1024 * sizeof(float));
        k_bnstat<<<256, 512>>>(p_proj, BB);
        k_bnfin<<<2, 256>>>(BB, 512);
        k_bnrelu<<<(BB * 512 + 255) / 256, 256>>>(p_proj, g_bng, g_bnb, BB, 512);

        dim3 go(768 / 128, (BB + 127) / 128);
        k_gemm<<<go, 256>>>(p_proj, g_w2, nullptr, p_head, BB, 768, 512, 0);

        k_l2<<<BB, 256>>>(p_head, dst, 768);
    }
}